// round 2
// baseline (speedup 1.0000x reference)
#include <cuda_runtime.h>
#include <cstdint>

// OrderParameter: C=30000 centrals, K=32 neighbors. One warp per central.
// Mask arrives as int32 (harness has no bool dtype).
//
//   v = vecs / ||vecs||;  cos[j1][j2] = clip(v_j1 . v_j2, -1, 1);  theta = acos(cos)
//   q_tet   = 1 - 3/(n(n-1)) * sum_offdiag (cos + 1/3)^2
//   q_tetra = sum_offdiag exp(-(th-109.47d)^2/(2*(10d)^2)) / (n(n-1))
//   q_oct:  term1 = 3*(th>160d)*exp(-(th-pi)^2/(2*(12d)^2))
//           term2(row) = 2.25 * (row_lt-1) * sum_{lt pairs} exp(-(th-pi/2)^2/(2*(10d)^2))
//           q_oct = sum(term1+term2) / (n*(3+(n-2)(n-3)))

#define FULLMASK 0xffffffffu

__global__ __launch_bounds__(256) void order_param_kernel(
    const float* __restrict__ vecs,  // [C, 32, 3] fp32
    const int*   __restrict__ mask,  // [C, 32] int32 (0/1)
    float* __restrict__ out,         // [3, C]
    int C)
{
    const int warp_global = (blockIdx.x * blockDim.x + threadIdx.x) >> 5;
    const int lane = threadIdx.x & 31;
    if (warp_global >= C) return;

    const float PI_F     = 3.14159265358979323846f;
    const float THETA0   = 109.47f * PI_F / 180.0f;
    const float THR      = 160.0f  * PI_F / 180.0f;
    const float HALF_PI  = 0.5f * PI_F;
    const float D_LT     = 10.0f * PI_F / 180.0f;
    const float D1       = 12.0f * PI_F / 180.0f;
    const float D2       = 10.0f * PI_F / 180.0f;
    const float NEG_I2DLT2 = -1.0f / (2.0f * D_LT * D_LT);
    const float NEG_I2D12  = -1.0f / (2.0f * D1 * D1);
    const float NEG_I2D22  = -1.0f / (2.0f * D2 * D2);

    // Own neighbor vector (warp reads 384B contiguous)
    const float* vp = vecs + (size_t)warp_global * 96 + lane * 3;
    const bool valid = mask[(size_t)warp_global * 32 + lane] != 0;
    float x = 0.0f, y = 0.0f, z = 1.0f;   // dummy for invalid lanes (avoid NaN)
    if (valid) { x = vp[0]; y = vp[1]; z = vp[2]; }
    float inv = rsqrtf(fmaf(x, x, fmaf(y, y, z * z)));
    x *= inv; y *= inv; z *= inv;

    const unsigned mm = __ballot_sync(FULLMASK, valid);

    float s_tet = 0.0f;
    float gsum  = 0.0f;
    float t1    = 0.0f;
    float e2s   = 0.0f;   // 2.25-weighted exp sum over lt pairs in this row
    int   row_lt = 0;

    #pragma unroll
    for (int j2 = 0; j2 < 32; j2++) {
        const float vx = __shfl_sync(FULLMASK, x, j2);
        const float vy = __shfl_sync(FULLMASK, y, j2);
        const float vz = __shfl_sync(FULLMASK, z, j2);
        const bool pv = valid && ((mm >> j2) & 1u) && (j2 != lane);
        if (pv) {
            float c = fmaf(x, vx, fmaf(y, vy, z * vz));
            c = fminf(1.0f, fmaxf(-1.0f, c));
            const float th = acosf(c);

            const float a = c + (1.0f / 3.0f);
            s_tet = fmaf(a, a, s_tet);

            const float d0 = th - THETA0;
            gsum += __expf(d0 * d0 * NEG_I2DLT2);

            if (th > THR) {
                const float dp = th - PI_F;
                t1 = fmaf(3.0f, __expf(dp * dp * NEG_I2D12), t1);
            } else if (th < THR) {
                row_lt++;
                const float dh = th - HALF_PI;
                e2s = fmaf(2.25f, __expf(dh * dh * NEG_I2D22), e2s);
            }
        }
    }

    float acc = t1 + e2s * (float)(row_lt - 1);

    #pragma unroll
    for (int o = 16; o > 0; o >>= 1) {
        s_tet += __shfl_xor_sync(FULLMASK, s_tet, o);
        gsum  += __shfl_xor_sync(FULLMASK, gsum,  o);
        acc   += __shfl_xor_sync(FULLMASK, acc,   o);
    }

    if (lane == 0) {
        const float n   = (float)__popc(mm);
        const float nn1 = n * (n - 1.0f);
        out[warp_global]         = 1.0f - 3.0f * s_tet / nn1;
        out[C + warp_global]     = gsum / nn1;
        out[2 * C + warp_global] = acc / (n * (3.0f + (n - 2.0f) * (n - 3.0f)));
    }
}

extern "C" void kernel_launch(void* const* d_in, const int* in_sizes, int n_in,
                              void* d_out, int out_size) {
    const float* vecs = (const float*)d_in[0];
    const int*   mask = (const int*)d_in[1];
    float* out = (float*)d_out;
    const int C = in_sizes[0] / (32 * 3);

    const int warps_per_block = 8;   // 256 threads
    const int blocks = (C + warps_per_block - 1) / warps_per_block;
    order_param_kernel<<<blocks, 256>>>(vecs, mask, out, C);
}

// round 3
// speedup vs baseline: 1.6773x; 1.6773x over previous
#include <cuda_runtime.h>
#include <cstdint>

// OrderParameter: C=30000 centrals, K=32 neighbors. One warp per central.
// Symmetric-pair formulation: loop over offsets o=1..16, lane j computes pair
// (j, (j+o)&31). Each unordered pair computed once (o=16 weighted 0.5).
// Row quantities for q_oct's term2 factorization get the mirror contribution
// from lane (j-o)&31 via shfl/ballot.
//
//   q_tet   = 1 - 3*S/(n(n-1)),      S = ordered-offdiag sum (cos+1/3)^2
//   q_tetra = G/(n(n-1)),            G = ordered sum exp(-(th-109.47d)^2/(2(10d)^2))
//   q_oct   = [T1 + sum_rows e2s_j*(row_lt_j-1)] / (n*(3+(n-2)(n-3)))
//             T1 = ordered sum 3*(th>160d)*exp(-(th-pi)^2/(2(12d)^2))
//             e2s_j = sum_{j2: lt} 2.25*exp(-(th-pi/2)^2/(2(10d)^2))

#define FULLMASK 0xffffffffu

__device__ __forceinline__ float fast_sqrt(float x) {
    float r; asm("sqrt.approx.f32 %0, %1;" : "=f"(r) : "f"(x)); return r;
}

// Abramowitz & Stegun 4.4.46: acos(x) = sqrt(1-x)*poly(x), |err|<=2e-8 rad on [0,1].
__device__ __forceinline__ float fast_acos(float c) {
    const float t = fabsf(c);
    float p = -0.0012624911f;
    p = fmaf(p, t,  0.0066700901f);
    p = fmaf(p, t, -0.0170881256f);
    p = fmaf(p, t,  0.0308918810f);
    p = fmaf(p, t, -0.0501743046f);
    p = fmaf(p, t,  0.0889789874f);
    p = fmaf(p, t, -0.2145988016f);
    p = fmaf(p, t,  1.5707963050f);
    const float r = fast_sqrt(1.0f - t) * p;
    return (c >= 0.0f) ? r : (3.14159265358979323846f - r);
}

__global__ __launch_bounds__(256) void order_param_kernel(
    const float* __restrict__ vecs,  // [C, 32, 3] fp32
    const int*   __restrict__ mask,  // [C, 32] int32 (0/1)
    float* __restrict__ out,         // [3, C]
    int C)
{
    const int warp_global = (blockIdx.x * blockDim.x + threadIdx.x) >> 5;
    const int lane = threadIdx.x & 31;
    if (warp_global >= C) return;

    const float PI_F     = 3.14159265358979323846f;
    const float THETA0   = 109.47f * PI_F / 180.0f;
    const float THR      = 160.0f  * PI_F / 180.0f;
    const float HALF_PI  = 0.5f * PI_F;
    const float D_LT     = 10.0f * PI_F / 180.0f;
    const float D1       = 12.0f * PI_F / 180.0f;
    const float D2       = 10.0f * PI_F / 180.0f;
    const float NEG_I2DLT2 = -1.0f / (2.0f * D_LT * D_LT);
    const float NEG_I2D12  = -1.0f / (2.0f * D1 * D1);
    const float NEG_I2D22  = -1.0f / (2.0f * D2 * D2);

    // Own neighbor vector (warp reads 384B contiguous)
    const float* vp = vecs + (size_t)warp_global * 96 + lane * 3;
    const bool valid = mask[(size_t)warp_global * 32 + lane] != 0;
    float x = 0.0f, y = 0.0f, z = 1.0f;   // dummy for invalid lanes (avoid NaN)
    if (valid) { x = vp[0]; y = vp[1]; z = vp[2]; }
    const float inv = rsqrtf(fmaf(x, x, fmaf(y, y, z * z)));
    x *= inv; y *= inv; z *= inv;

    const unsigned mm = __ballot_sync(FULLMASK, valid);

    float s_acc  = 0.0f;   // unordered (cos+1/3)^2 sum (o=16 half-weighted)
    float g_acc  = 0.0f;   // unordered tetra gaussian sum
    float t1_acc = 0.0f;   // unordered term1 sum
    float e2s    = 0.0f;   // row-j 2.25-weighted exp2 sum (ordered, full)
    int   row_lt = 0;      // row-j lt-pair count (ordered, full)

    #pragma unroll
    for (int o = 1; o <= 16; o++) {
        const int p = (lane + o) & 31;
        const float vx = __shfl_sync(FULLMASK, x, p);
        const float vy = __shfl_sync(FULLMASK, y, p);
        const float vz = __shfl_sync(FULLMASK, z, p);
        const bool pv = valid && ((mm >> p) & 1u);
        const float w = pv ? 1.0f : 0.0f;

        float c = fmaf(x, vx, fmaf(y, vy, z * vz));
        c = fminf(1.0f, fmaxf(-1.0f, c));
        const float th = fast_acos(c);

        const float a  = c + (1.0f / 3.0f);
        const float s_p = w * a * a;

        const float d0 = th - THETA0;
        const float g_p = w * __expf(d0 * d0 * NEG_I2DLT2);

        const float dpi = th - PI_F;
        const float t1_p = (th > THR) ? (3.0f * w * __expf(dpi * dpi * NEG_I2D12)) : 0.0f;

        const bool lt = pv && (th < THR);
        const float dh = th - HALF_PI;
        const float e2_p = lt ? (2.25f * __expf(dh * dh * NEG_I2D22)) : 0.0f;

        const unsigned ltm = __ballot_sync(FULLMASK, lt);

        if (o < 16) {
            s_acc  += s_p;
            g_acc  += g_p;
            t1_acc += t1_p;
            const int q = (lane - o) & 31;
            const float e2_in = __shfl_sync(FULLMASK, e2_p, q);   // pair (q, lane) == row-j pair (j, j-o)
            e2s += e2_p + e2_in;
            row_lt += (int)((ltm >> lane) & 1u) + (int)((ltm >> q) & 1u);
        } else {
            // d=16 pairs computed by both endpoints: half-weight symmetric sums,
            // own-only for row quantities (covers ordered (j, j+16) exactly).
            s_acc  = fmaf(0.5f, s_p,  s_acc);
            g_acc  = fmaf(0.5f, g_p,  g_acc);
            t1_acc = fmaf(0.5f, t1_p, t1_acc);
            e2s += e2_p;
            row_lt += (int)((ltm >> lane) & 1u);
        }
    }

    // Ordered totals: symmetric sums double; term2 uses per-row values.
    float S = 2.0f * s_acc;
    float G = 2.0f * g_acc;
    float O = fmaf(e2s, (float)(row_lt - 1), 2.0f * t1_acc);

    #pragma unroll
    for (int off = 16; off > 0; off >>= 1) {
        S += __shfl_xor_sync(FULLMASK, S, off);
        G += __shfl_xor_sync(FULLMASK, G, off);
        O += __shfl_xor_sync(FULLMASK, O, off);
    }

    if (lane == 0) {
        const float n   = (float)__popc(mm);
        const float nn1 = n * (n - 1.0f);
        out[warp_global]         = 1.0f - 3.0f * S / nn1;
        out[C + warp_global]     = G / nn1;
        out[2 * C + warp_global] = O / (n * (3.0f + (n - 2.0f) * (n - 3.0f)));
    }
}

extern "C" void kernel_launch(void* const* d_in, const int* in_sizes, int n_in,
                              void* d_out, int out_size) {
    const float* vecs = (const float*)d_in[0];
    const int*   mask = (const int*)d_in[1];
    float* out = (float*)d_out;
    const int C = in_sizes[0] / (32 * 3);

    const int warps_per_block = 8;   // 256 threads
    const int blocks = (C + warps_per_block - 1) / warps_per_block;
    order_param_kernel<<<blocks, 256>>>(vecs, mask, out, C);
}

// round 4
// speedup vs baseline: 2.0986x; 1.2512x over previous
#include <cuda_runtime.h>
#include <cstdint>

// OrderParameter: C=30000 centrals, K=32 neighbors. One warp per central.
// Fast path (mask all-ones, the benchmark case): symmetric-pair loop packed
// two offsets per step into f32x2 (FFMA2) registers. Offsets paired (o, o+8),
// o=1..8, covering o=1..16; o=16 handled with half weight for symmetric sums
// and own-only row accumulation (each unordered pair once).
// Generic fallback path = verified R3 loop.
//
//   q_tet   = 1 - 3*S/(n(n-1))
//   q_tetra = G/(n(n-1))
//   q_oct   = [2*T1 + sum_rows e2s_j*(row_lt_j-1)] / (n*(3+(n-2)(n-3)))
//
// row_lt and e2s travel together in one float: val = 2.25*e + 256*lt.
// Accumulated v = e2s + 256*row_lt <= ~8006; recovered with floor(v/256+0.03).
// Worst-case rounding leakage into q_oct ~5e-4 absolute vs q_oct ~O(0.5).

#define FULLMASK 0xffffffffu

__device__ __forceinline__ float ex2f(float x) {
    float r; asm("ex2.approx.f32 %0, %1;" : "=f"(r) : "f"(x)); return r;
}
__device__ __forceinline__ float sqrt_ap(float x) {
    float r; asm("sqrt.approx.f32 %0, %1;" : "=f"(r) : "f"(x)); return r;
}

// ---- f32x2 packed helpers ----
__device__ __forceinline__ uint64_t pk2(float lo, float hi) {
    uint64_t d; asm("mov.b64 %0, {%1, %2};" : "=l"(d) : "f"(lo), "f"(hi)); return d;
}
__device__ __forceinline__ void upk2(uint64_t d, float& lo, float& hi) {
    asm("mov.b64 {%0, %1}, %2;" : "=f"(lo), "=f"(hi) : "l"(d));
}
__device__ __forceinline__ uint64_t bc2(float v) { return pk2(v, v); }
__device__ __forceinline__ uint64_t f2mul(uint64_t a, uint64_t b) {
    uint64_t d; asm("mul.rn.f32x2 %0, %1, %2;" : "=l"(d) : "l"(a), "l"(b)); return d;
}
__device__ __forceinline__ uint64_t f2add(uint64_t a, uint64_t b) {
    uint64_t d; asm("add.rn.f32x2 %0, %1, %2;" : "=l"(d) : "l"(a), "l"(b)); return d;
}
__device__ __forceinline__ uint64_t f2fma(uint64_t a, uint64_t b, uint64_t c) {
    uint64_t d; asm("fma.rn.f32x2 %0, %1, %2, %3;" : "=l"(d) : "l"(a), "l"(b), "l"(c)); return d;
}

// ---- constants ----
#define PI_F      3.14159265358979323846f
#define HALF_PI_F 1.57079632679489661923f
#define THETA0_F  1.91061193216957395f     // 109.47 deg
#define THR_F     2.79252680319092716f     // 160 deg
#define COS_THR_F (-0.93969262078590838f)  // cos(160 deg)
#define LOG2E_F   1.44269504088896340f
#define D_LT_F    0.17453292519943295f     // 10 deg
#define D1_F      0.20943951023931953f     // 12 deg
// exp2 arguments: fold log2(e) into the Gaussian width constants
#define KG_F  (-LOG2E_F / (2.0f * D_LT_F * D_LT_F))   // tetra gaussian
#define K1_F  (-LOG2E_F / (2.0f * D1_F  * D1_F ))     // term1 (theta>160)
#define K2_F  (-LOG2E_F / (2.0f * D_LT_F * D_LT_F))   // term2 (10 deg width)

// One packed step: offsets (o0, o1) for this lane. mirror_hi: whether o1's
// mirror contribution is accumulated (false only for o1==16).
__device__ __forceinline__ void pair_step(
    uint64_t x2, uint64_t y2, uint64_t z2,
    float x, float y, float z, int lane, int o0, int o1,
    bool mirror_hi, uint64_t W2,
    uint64_t& s2, uint64_t& g2, uint64_t& t12, uint64_t& v2, uint64_t& m2)
{
    const int pl = (lane + o0) & 31;
    const int ph = (lane + o1) & 31;
    const uint64_t vx2 = pk2(__shfl_sync(FULLMASK, x, pl), __shfl_sync(FULLMASK, x, ph));
    const uint64_t vy2 = pk2(__shfl_sync(FULLMASK, y, pl), __shfl_sync(FULLMASK, y, ph));
    const uint64_t vz2 = pk2(__shfl_sync(FULLMASK, z, pl), __shfl_sync(FULLMASK, z, ph));

    // packed dot product (|c| can exceed 1 by ~1 ulp; handled below)
    const uint64_t c2 = f2fma(x2, vx2, f2fma(y2, vy2, f2mul(z2, vz2)));

    // q_tet contribution: (c + 1/3)^2
    const uint64_t a2 = f2add(c2, bc2(1.0f / 3.0f));
    s2 = f2fma(f2mul(a2, a2), W2, s2);

    // acos via A&S 4.4.46, packed: acos(|c|) = sqrt(1-|c|)*poly(|c|)
    const uint64_t t2 = c2 & 0x7FFFFFFF7FFFFFFFull;
    uint64_t p2 = bc2(-0.0012624911f);
    p2 = f2fma(p2, t2, bc2( 0.0066700901f));
    p2 = f2fma(p2, t2, bc2(-0.0170881256f));
    p2 = f2fma(p2, t2, bc2( 0.0308918810f));
    p2 = f2fma(p2, t2, bc2(-0.0501743046f));
    p2 = f2fma(p2, t2, bc2( 0.0889789874f));
    p2 = f2fma(p2, t2, bc2(-0.2145988016f));
    p2 = f2fma(p2, t2, bc2( 1.5707963050f));
    const uint64_t om2 = f2fma(t2, bc2(-1.0f), bc2(1.0f));   // 1 - |c|
    float omlo, omhi; upk2(om2, omlo, omhi);
    const uint64_t sq2 = pk2(sqrt_ap(fmaxf(omlo, 0.0f)), sqrt_ap(fmaxf(omhi, 0.0f)));
    const uint64_t r2 = f2mul(sq2, p2);                      // acos(|c|) in [0, pi/2]
    // theta = pi/2 - copysign(pi/2 - r, c);  (pi/2 - r) >= 0 so OR the sign bit
    const uint64_t u2 = f2fma(r2, bc2(-1.0f), bc2(HALF_PI_F));
    const uint64_t cs2 = u2 | (c2 & 0x8000000080000000ull);
    const uint64_t th2 = f2fma(cs2, bc2(-1.0f), bc2(HALF_PI_F));

    // tetra gaussian
    const uint64_t d0 = f2add(th2, bc2(-THETA0_F));
    const uint64_t ag = f2mul(f2mul(d0, bc2(KG_F)), d0);
    float aglo, aghi; upk2(ag, aglo, aghi);
    g2 = f2fma(pk2(ex2f(aglo), ex2f(aghi)), W2, g2);

    // term1 / term2 arguments (mutually exclusive on theta vs 160 deg)
    const uint64_t dA = f2add(th2, bc2(-PI_F));
    const uint64_t argA = f2mul(f2mul(dA, bc2(K1_F)), dA);
    const uint64_t dB = f2add(th2, bc2(-HALF_PI_F));
    const uint64_t argB = f2mul(f2mul(dB, bc2(K2_F)), dB);

    float clo, chi; upk2(c2, clo, chi);
    float aAlo, aAhi; upk2(argA, aAlo, aAhi);
    float aBlo, aBhi; upk2(argB, aBlo, aBhi);

    const bool gtlo = clo < COS_THR_F;          // theta > 160deg
    const bool gthi = chi < COS_THR_F;
    const float elo = ex2f(gtlo ? aAlo : aBlo);
    const float ehi = ex2f(gthi ? aAhi : aBhi);
    const float t1lo = gtlo ? 3.0f * elo : 0.0f;
    const float t1hi = gthi ? 3.0f * ehi : 0.0f;
    const float vallo = gtlo ? 0.0f : fmaf(2.25f, elo, 256.0f);
    const float valhi = gthi ? 0.0f : fmaf(2.25f, ehi, 256.0f);

    t12 = f2fma(pk2(t1lo, t1hi), W2, t12);
    v2  = f2add(v2, pk2(vallo, valhi));

    // mirror: row j receives pair (j-o, j) from lane j-o at the same offset
    const float mlo = __shfl_sync(FULLMASK, vallo, (lane - o0) & 31);
    float mhi = 0.0f;
    if (mirror_hi) mhi = __shfl_sync(FULLMASK, valhi, (lane - o1) & 31);
    m2 = f2add(m2, pk2(mlo, mhi));
}

__global__ __launch_bounds__(256) void order_param_kernel(
    const float* __restrict__ vecs,  // [C, 32, 3]
    const int*   __restrict__ mask,  // [C, 32] int32 0/1
    float* __restrict__ out,         // [3, C]
    int C)
{
    const int warp_global = (blockIdx.x * blockDim.x + threadIdx.x) >> 5;
    const int lane = threadIdx.x & 31;
    if (warp_global >= C) return;

    const float* vp = vecs + (size_t)warp_global * 96 + lane * 3;
    const bool valid = mask[(size_t)warp_global * 32 + lane] != 0;
    float x = 0.0f, y = 0.0f, z = 1.0f;
    if (valid) { x = vp[0]; y = vp[1]; z = vp[2]; }
    const float inv = rsqrtf(fmaf(x, x, fmaf(y, y, z * z)));
    x *= inv; y *= inv; z *= inv;

    const unsigned mm = __ballot_sync(FULLMASK, valid);

    float S, G, O;   // ordered sums (per-lane partials before warp reduce)

    if (mm == FULLMASK) {
        // ---------- fast path: all 32 neighbors valid ----------
        const uint64_t x2 = bc2(x), y2 = bc2(y), z2 = bc2(z);
        uint64_t s2 = 0, g2 = 0, t12 = 0, v2 = 0, m2 = 0;
        const uint64_t W1 = bc2(1.0f);

        #pragma unroll
        for (int k = 0; k < 7; k++)   // offsets (1..7, 9..15)
            pair_step(x2, y2, z2, x, y, z, lane, k + 1, k + 9, true, W1,
                      s2, g2, t12, v2, m2);
        // peeled step: offsets (8, 16); o=16 own-only, half weight symmetric
        pair_step(x2, y2, z2, x, y, z, lane, 8, 16, false, pk2(1.0f, 0.5f),
                  s2, g2, t12, v2, m2);

        float slo, shi, glo, ghi, tlo, thi, vlo, vhi, mlo, mhi;
        upk2(s2, slo, shi); upk2(g2, glo, ghi); upk2(t12, tlo, thi);
        upk2(v2, vlo, vhi); upk2(m2, mlo, mhi);

        S = 2.0f * (slo + shi);
        G = 2.0f * (glo + ghi);
        const float v = (vlo + vhi) + (mlo + mhi);       // e2s + 256*row_lt
        const float cnt = floorf(fmaf(v, 1.0f / 256.0f, 0.03f));
        const float e2s = fmaf(-256.0f, cnt, v);
        O = fmaf(e2s, cnt - 1.0f, 2.0f * (tlo + thi));
    } else {
        // ---------- generic path (verified R3 loop) ----------
        const float NEG_I2DLT2 = -1.0f / (2.0f * D_LT_F * D_LT_F);
        const float NEG_I2D12  = -1.0f / (2.0f * D1_F * D1_F);

        float s_acc = 0.0f, g_acc = 0.0f, t1_acc = 0.0f, e2s = 0.0f;
        int row_lt = 0;
        #pragma unroll
        for (int o = 1; o <= 16; o++) {
            const int p = (lane + o) & 31;
            const float vx = __shfl_sync(FULLMASK, x, p);
            const float vy = __shfl_sync(FULLMASK, y, p);
            const float vz = __shfl_sync(FULLMASK, z, p);
            const bool pv = valid && ((mm >> p) & 1u);
            const float w = pv ? 1.0f : 0.0f;

            float c = fmaf(x, vx, fmaf(y, vy, z * vz));
            c = fminf(1.0f, fmaxf(-1.0f, c));
            const float th = acosf(c);

            const float a = c + (1.0f / 3.0f);
            const float s_p = w * a * a;
            const float d0 = th - THETA0_F;
            const float g_p = w * __expf(d0 * d0 * NEG_I2DLT2);
            const float dpi = th - PI_F;
            const float t1_p = (th > THR_F) ? (3.0f * w * __expf(dpi * dpi * NEG_I2D12)) : 0.0f;
            const bool lt = pv && (th < THR_F);
            const float dh = th - HALF_PI_F;
            const float e2_p = lt ? (2.25f * __expf(dh * dh * NEG_I2DLT2)) : 0.0f;
            const unsigned ltm = __ballot_sync(FULLMASK, lt);

            if (o < 16) {
                s_acc += s_p; g_acc += g_p; t1_acc += t1_p;
                const int q = (lane - o) & 31;
                e2s += e2_p + __shfl_sync(FULLMASK, e2_p, q);
                row_lt += (int)((ltm >> lane) & 1u) + (int)((ltm >> q) & 1u);
            } else {
                s_acc  = fmaf(0.5f, s_p,  s_acc);
                g_acc  = fmaf(0.5f, g_p,  g_acc);
                t1_acc = fmaf(0.5f, t1_p, t1_acc);
                e2s += e2_p;
                row_lt += (int)((ltm >> lane) & 1u);
            }
        }
        S = 2.0f * s_acc;
        G = 2.0f * g_acc;
        O = fmaf(e2s, (float)(row_lt - 1), 2.0f * t1_acc);
    }

    #pragma unroll
    for (int off = 16; off > 0; off >>= 1) {
        S += __shfl_xor_sync(FULLMASK, S, off);
        G += __shfl_xor_sync(FULLMASK, G, off);
        O += __shfl_xor_sync(FULLMASK, O, off);
    }

    if (lane == 0) {
        const float n   = (float)__popc(mm);
        const float nn1 = n * (n - 1.0f);
        out[warp_global]         = 1.0f - 3.0f * S / nn1;
        out[C + warp_global]     = G / nn1;
        out[2 * C + warp_global] = O / (n * (3.0f + (n - 2.0f) * (n - 3.0f)));
    }
}

extern "C" void kernel_launch(void* const* d_in, const int* in_sizes, int n_in,
                              void* d_out, int out_size) {
    const float* vecs = (const float*)d_in[0];
    const int*   mask = (const int*)d_in[1];
    float* out = (float*)d_out;
    const int C = in_sizes[0] / (32 * 3);

    const int warps_per_block = 8;   // 256 threads
    const int blocks = (C + warps_per_block - 1) / warps_per_block;
    order_param_kernel<<<blocks, 256>>>(vecs, mask, out, C);
}

// round 5
// speedup vs baseline: 2.3115x; 1.1014x over previous
#include <cuda_runtime.h>
#include <cstdint>

// OrderParameter: C=30000 centrals, K=32 neighbors. One warp per central.
// Fast path (mask all-ones): symmetric-pair loop over offsets o=1..16, lane j
// computes pair (j,(j+o)&31); offsets packed (o, o+8) into f32x2 through the
// acos chain, then scalar immediate-form tail. o=16 half-weighted for the
// symmetric sums, own-only for row quantities.
//
//   q_tet   = 1 - 3*S/(n(n-1))
//   q_tetra = G/(n(n-1))
//   q_oct   = [2*T1 + sum_rows e2s_j*(row_lt_j-1)] / (n*(3+(n-2)(n-3)))
//
// row_lt and e2s travel in one float: val = 2.25*e + 256*lt (v < 8006,
// recovered with floor(v/256+0.03); worst-case leakage into q_oct ~2e-5).

#define FULLMASK 0xffffffffu

__device__ __forceinline__ float ex2f(float x) {
    float r; asm("ex2.approx.f32 %0, %1;" : "=f"(r) : "f"(x)); return r;
}
__device__ __forceinline__ float sqrt_ap(float x) {
    float r; asm("sqrt.approx.f32 %0, %1;" : "=f"(r) : "f"(x)); return r;
}

// ---- f32x2 packed helpers ----
__device__ __forceinline__ uint64_t pk2(float lo, float hi) {
    uint64_t d; asm("mov.b64 %0, {%1, %2};" : "=l"(d) : "f"(lo), "f"(hi)); return d;
}
__device__ __forceinline__ void upk2(uint64_t d, float& lo, float& hi) {
    asm("mov.b64 {%0, %1}, %2;" : "=f"(lo), "=f"(hi) : "l"(d));
}
__device__ __forceinline__ uint64_t bc2(float v) { return pk2(v, v); }
__device__ __forceinline__ uint64_t f2mul(uint64_t a, uint64_t b) {
    uint64_t d; asm("mul.rn.f32x2 %0, %1, %2;" : "=l"(d) : "l"(a), "l"(b)); return d;
}
__device__ __forceinline__ uint64_t f2add(uint64_t a, uint64_t b) {
    uint64_t d; asm("add.rn.f32x2 %0, %1, %2;" : "=l"(d) : "l"(a), "l"(b)); return d;
}
__device__ __forceinline__ uint64_t f2fma(uint64_t a, uint64_t b, uint64_t c) {
    uint64_t d; asm("fma.rn.f32x2 %0, %1, %2, %3;" : "=l"(d) : "l"(a), "l"(b), "l"(c)); return d;
}

// ---- constants ----
#define PI_F      3.14159265358979323846f
#define HALF_PI_F 1.57079632679489661923f
#define THETA0_F  1.91061193216957395f     // 109.47 deg
#define THR_F     2.79252680319092716f     // 160 deg
#define COS_THR_F (-0.93969262078590838f)  // cos(160 deg)
#define LOG2E_F   1.44269504088896340f
#define D_LT_F    0.17453292519943295f     // 10 deg
#define D1_F      0.20943951023931953f     // 12 deg
#define KG_F  (-LOG2E_F / (2.0f * D_LT_F * D_LT_F))   // tetra gaussian (theta0)
#define K1_F  (-LOG2E_F / (2.0f * D1_F  * D1_F ))     // term1 (center pi)
#define K2_F  (-LOG2E_F / (2.0f * D_LT_F * D_LT_F))   // term2 (center pi/2)

// Scalar immediate-form tail for one pair: tetra gaussian + term1/term2.
// wsym: weight for the symmetric sums (1 or 0.5). Returns packed val
// (2.25*e2 + 256) for lt pairs, 0 for gt pairs.
__device__ __forceinline__ float half_tail(float th, float c, float wsym,
                                           float& g, float& t1)
{
    const float d0 = th - THETA0_F;
    g = fmaf(ex2f((KG_F * d0) * d0), wsym, g);

    const bool gt  = c < COS_THR_F;          // theta > 160deg (acos monotone dec)
    const float ctr = gt ? PI_F : HALF_PI_F;
    const float kk  = gt ? K1_F : K2_F;
    const float d   = th - ctr;
    const float e   = ex2f((kk * d) * d);
    t1 = fmaf(gt ? 3.0f * wsym : 0.0f, e, t1);
    return gt ? 0.0f : fmaf(2.25f, e, 256.0f);
}

// One packed step: offsets (o0, o1). last==true => o1==16 (half-weight
// symmetric, own-only row accumulation for hi).
__device__ __forceinline__ void pair_step(
    uint64_t x2, uint64_t y2, uint64_t z2,
    float x, float y, float z, int lane, int o0, int o1, bool last,
    uint64_t& s2, float& g, float& t1, float& vo, float& vm)
{
    const int pl = (lane + o0) & 31;
    const int ph = (lane + o1) & 31;
    const uint64_t vx2 = pk2(__shfl_sync(FULLMASK, x, pl), __shfl_sync(FULLMASK, x, ph));
    const uint64_t vy2 = pk2(__shfl_sync(FULLMASK, y, pl), __shfl_sync(FULLMASK, y, ph));
    const uint64_t vz2 = pk2(__shfl_sync(FULLMASK, z, pl), __shfl_sync(FULLMASK, z, ph));

    const uint64_t c2 = f2fma(x2, vx2, f2fma(y2, vy2, f2mul(z2, vz2)));

    // q_tet: (c + 1/3)^2, half-weight hi on last step
    const uint64_t a2  = f2add(c2, bc2(1.0f / 3.0f));
    const uint64_t aa2 = f2mul(a2, a2);
    s2 = last ? f2fma(aa2, pk2(1.0f, 0.5f), s2) : f2add(aa2, s2);

    // packed acos (A&S 4.4.46): acos(|c|) = sqrt(1-|c|)*poly(|c|)
    const uint64_t t2 = c2 & 0x7FFFFFFF7FFFFFFFull;
    uint64_t p2 = bc2(-0.0012624911f);
    p2 = f2fma(p2, t2, bc2( 0.0066700901f));
    p2 = f2fma(p2, t2, bc2(-0.0170881256f));
    p2 = f2fma(p2, t2, bc2( 0.0308918810f));
    p2 = f2fma(p2, t2, bc2(-0.0501743046f));
    p2 = f2fma(p2, t2, bc2( 0.0889789874f));
    p2 = f2fma(p2, t2, bc2(-0.2145988016f));
    p2 = f2fma(p2, t2, bc2( 1.5707963050f));
    const uint64_t om2 = f2fma(t2, bc2(-1.0f), bc2(1.0f));   // 1-|c| (>= -2e-7)
    float omlo, omhi; upk2(om2, omlo, omhi);
    const uint64_t sq2 = pk2(sqrt_ap(fmaxf(omlo, 0.0f)), sqrt_ap(fmaxf(omhi, 0.0f)));
    const uint64_t r2 = f2mul(sq2, p2);                      // acos(|c|)
    // theta = pi/2 - ((pi/2 - r) | signbit(c))
    const uint64_t u2  = f2fma(r2, bc2(-1.0f), bc2(HALF_PI_F));
    const uint64_t cs2 = u2 | (c2 & 0x8000000080000000ull);
    const uint64_t th2 = f2fma(cs2, bc2(-1.0f), bc2(HALF_PI_F));

    float thlo, thhi; upk2(th2, thlo, thhi);
    float clo, chi;   upk2(c2, clo, chi);

    const float vlo = half_tail(thlo, clo, 1.0f, g, t1);
    const float vhi = half_tail(thhi, chi, last ? 0.5f : 1.0f, g, t1);

    vo += vlo + vhi;
    vm += __shfl_sync(FULLMASK, vlo, (lane - o0) & 31);
    const float mh = __shfl_sync(FULLMASK, vhi, (lane - o1) & 31);
    if (!last) vm += mh;
}

__global__ __launch_bounds__(256) void order_param_kernel(
    const float* __restrict__ vecs,  // [C, 32, 3]
    const int*   __restrict__ mask,  // [C, 32] int32 0/1
    float* __restrict__ out,         // [3, C]
    int C)
{
    const int warp_global = (blockIdx.x * blockDim.x + threadIdx.x) >> 5;
    const int lane = threadIdx.x & 31;
    if (warp_global >= C) return;

    const float* vp = vecs + (size_t)warp_global * 96 + lane * 3;
    const bool valid = mask[(size_t)warp_global * 32 + lane] != 0;
    float x = 0.0f, y = 0.0f, z = 1.0f;
    if (valid) { x = vp[0]; y = vp[1]; z = vp[2]; }
    const float inv = rsqrtf(fmaf(x, x, fmaf(y, y, z * z)));
    x *= inv; y *= inv; z *= inv;

    const unsigned mm = __ballot_sync(FULLMASK, valid);

    float S, G, O;

    if (mm == FULLMASK) {
        // ---------- fast path: all 32 neighbors valid ----------
        const uint64_t x2 = bc2(x), y2 = bc2(y), z2 = bc2(z);
        uint64_t s2 = 0;
        float g = 0.0f, t1 = 0.0f, vo = 0.0f, vm = 0.0f;

        #pragma unroll
        for (int k = 0; k < 7; k++)   // offsets (1..7, 9..15)
            pair_step(x2, y2, z2, x, y, z, lane, k + 1, k + 9, false,
                      s2, g, t1, vo, vm);
        pair_step(x2, y2, z2, x, y, z, lane, 8, 16, true,
                  s2, g, t1, vo, vm);

        float slo, shi; upk2(s2, slo, shi);
        S = 2.0f * (slo + shi);
        G = 2.0f * g;
        const float v   = vo + vm;                          // e2s + 256*row_lt
        const float cnt = floorf(fmaf(v, 1.0f / 256.0f, 0.03f));
        const float e2s = fmaf(-256.0f, cnt, v);
        O = fmaf(e2s, cnt - 1.0f, 2.0f * t1);
    } else {
        // ---------- generic path (verified R3 loop) ----------
        const float NEG_I2DLT2 = -1.0f / (2.0f * D_LT_F * D_LT_F);
        const float NEG_I2D12  = -1.0f / (2.0f * D1_F * D1_F);

        float s_acc = 0.0f, g_acc = 0.0f, t1_acc = 0.0f, e2s = 0.0f;
        int row_lt = 0;
        #pragma unroll
        for (int o = 1; o <= 16; o++) {
            const int p = (lane + o) & 31;
            const float vx = __shfl_sync(FULLMASK, x, p);
            const float vy = __shfl_sync(FULLMASK, y, p);
            const float vz = __shfl_sync(FULLMASK, z, p);
            const bool pv = valid && ((mm >> p) & 1u);
            const float w = pv ? 1.0f : 0.0f;

            float c = fmaf(x, vx, fmaf(y, vy, z * vz));
            c = fminf(1.0f, fmaxf(-1.0f, c));
            const float th = acosf(c);

            const float a = c + (1.0f / 3.0f);
            const float s_p = w * a * a;
            const float d0 = th - THETA0_F;
            const float g_p = w * __expf(d0 * d0 * NEG_I2DLT2);
            const float dpi = th - PI_F;
            const float t1_p = (th > THR_F) ? (3.0f * w * __expf(dpi * dpi * NEG_I2D12)) : 0.0f;
            const bool lt = pv && (th < THR_F);
            const float dh = th - HALF_PI_F;
            const float e2_p = lt ? (2.25f * __expf(dh * dh * NEG_I2DLT2)) : 0.0f;
            const unsigned ltm = __ballot_sync(FULLMASK, lt);

            if (o < 16) {
                s_acc += s_p; g_acc += g_p; t1_acc += t1_p;
                const int q = (lane - o) & 31;
                e2s += e2_p + __shfl_sync(FULLMASK, e2_p, q);
                row_lt += (int)((ltm >> lane) & 1u) + (int)((ltm >> q) & 1u);
            } else {
                s_acc  = fmaf(0.5f, s_p,  s_acc);
                g_acc  = fmaf(0.5f, g_p,  g_acc);
                t1_acc = fmaf(0.5f, t1_p, t1_acc);
                e2s += e2_p;
                row_lt += (int)((ltm >> lane) & 1u);
            }
        }
        S = 2.0f * s_acc;
        G = 2.0f * g_acc;
        O = fmaf(e2s, (float)(row_lt - 1), 2.0f * t1_acc);
    }

    #pragma unroll
    for (int off = 16; off > 0; off >>= 1) {
        S += __shfl_xor_sync(FULLMASK, S, off);
        G += __shfl_xor_sync(FULLMASK, G, off);
        O += __shfl_xor_sync(FULLMASK, O, off);
    }

    if (lane == 0) {
        const float n   = (float)__popc(mm);
        const float nn1 = n * (n - 1.0f);
        out[warp_global]         = 1.0f - 3.0f * S / nn1;
        out[C + warp_global]     = G / nn1;
        out[2 * C + warp_global] = O / (n * (3.0f + (n - 2.0f) * (n - 3.0f)));
    }
}

extern "C" void kernel_launch(void* const* d_in, const int* in_sizes, int n_in,
                              void* d_out, int out_size) {
    const float* vecs = (const float*)d_in[0];
    const int*   mask = (const int*)d_in[1];
    float* out = (float*)d_out;
    const int C = in_sizes[0] / (32 * 3);

    const int warps_per_block = 8;   // 256 threads
    const int blocks = (C + warps_per_block - 1) / warps_per_block;
    order_param_kernel<<<blocks, 256>>>(vecs, mask, out, C);
}

// round 6
// speedup vs baseline: 2.3138x; 1.0010x over previous
#include <cuda_runtime.h>
#include <cstdint>

// OrderParameter: C=30000 centrals, K=32 neighbors. One warp per central.
// Fast path (mask all-ones): symmetric-pair loop over offsets o=1..16; lane j
// computes pair (j, j+o mod 32). Offsets packed (o, o+8) in f32x2 through the
// dot/acos/gaussian-arg chain; scalar immediate-form accumulation tail.
// o=16 half-weighted for symmetric sums, own-only for row quantities.
//
//   q_tet   = 1 - 3*S/(n(n-1))
//   q_tetra = G/(n(n-1))
//   q_oct   = [2*T1 + sum_rows e2s_j*(row_lt_j-1)] / (n*(3+(n-2)(n-3)))
//
// row_lt/e2s packed per row: val = 2.25*e2 + 256 for lt pairs, 0 for gt.
// v <= 8006; cnt = floor(v/256 + 0.03) is exact (e2s/256 <= 0.28 < 0.97).

#define FULLMASK 0xffffffffu

__device__ __forceinline__ float ex2f(float x) {
    float r; asm("ex2.approx.f32 %0, %1;" : "=f"(r) : "f"(x)); return r;
}
__device__ __forceinline__ float sqrt_ap(float x) {
    float r; asm("sqrt.approx.f32 %0, %1;" : "=f"(r) : "f"(x)); return r;
}

// ---- f32x2 packed helpers ----
__device__ __forceinline__ uint64_t pk2(float lo, float hi) {
    uint64_t d; asm("mov.b64 %0, {%1, %2};" : "=l"(d) : "f"(lo), "f"(hi)); return d;
}
__device__ __forceinline__ void upk2(uint64_t d, float& lo, float& hi) {
    asm("mov.b64 {%0, %1}, %2;" : "=f"(lo), "=f"(hi) : "l"(d));
}
__device__ __forceinline__ uint64_t bc2(float v) { return pk2(v, v); }
__device__ __forceinline__ uint64_t f2mul(uint64_t a, uint64_t b) {
    uint64_t d; asm("mul.rn.f32x2 %0, %1, %2;" : "=l"(d) : "l"(a), "l"(b)); return d;
}
__device__ __forceinline__ uint64_t f2add(uint64_t a, uint64_t b) {
    uint64_t d; asm("add.rn.f32x2 %0, %1, %2;" : "=l"(d) : "l"(a), "l"(b)); return d;
}
__device__ __forceinline__ uint64_t f2fma(uint64_t a, uint64_t b, uint64_t c) {
    uint64_t d; asm("fma.rn.f32x2 %0, %1, %2, %3;" : "=l"(d) : "l"(a), "l"(b), "l"(c)); return d;
}

// ---- constants ----
#define PI_F      3.14159265358979323846f
#define HALF_PI_F 1.57079632679489661923f
#define THETA0_F  1.91061193216957395f     // 109.47 deg
#define THR_F     2.79252680319092716f     // 160 deg
#define COS_THR_F (-0.93969262078590838f)  // cos(160 deg)
#define LOG2E_F   1.44269504088896340f
#define D_LT_F    0.17453292519943295f     // 10 deg
#define D1_F      0.20943951023931953f     // 12 deg
#define KG_F  (-LOG2E_F / (2.0f * D_LT_F * D_LT_F))   // tetra gaussian (theta0)
#define K1_F  (-LOG2E_F / (2.0f * D1_F  * D1_F ))     // term1 (center pi)
#define K2_F  (-LOG2E_F / (2.0f * D_LT_F * D_LT_F))   // term2 (center pi/2)

// One packed step: offsets (O0, O1). LAST => O1==16: half-weight symmetric
// sums for hi, own-only row accumulation for hi.
template<int O0, int O1, bool LAST>
__device__ __forceinline__ void pair_step(
    uint64_t x2, uint64_t y2, uint64_t z2,
    float x, float y, float z, int lane,
    uint64_t& s2, float& g, float& t1, float& vo, float& vm)
{
    // modulo-wrap shuffles (documented srcLane % width semantics)
    const float xl = __shfl_sync(FULLMASK, x, lane + O0);
    const float yl = __shfl_sync(FULLMASK, y, lane + O0);
    const float zl = __shfl_sync(FULLMASK, z, lane + O0);
    const float xh = __shfl_sync(FULLMASK, x, lane + O1);
    const float yh = __shfl_sync(FULLMASK, y, lane + O1);
    const float zh = __shfl_sync(FULLMASK, z, lane + O1);
    const uint64_t vx2 = pk2(xl, xh);
    const uint64_t vy2 = pk2(yl, yh);
    const uint64_t vz2 = pk2(zl, zh);

    const uint64_t c2 = f2fma(x2, vx2, f2fma(y2, vy2, f2mul(z2, vz2)));

    // q_tet: (c + 1/3)^2, hi half-weight on last step
    const uint64_t a2  = f2add(c2, bc2(1.0f / 3.0f));
    const uint64_t aa2 = f2mul(a2, a2);
    s2 = LAST ? f2fma(aa2, pk2(1.0f, 0.5f), s2) : f2add(aa2, s2);

    // packed acos (A&S 4.4.46): acos(|c|) = sqrt(1-|c|)*poly(|c|)
    const uint64_t t2 = c2 & 0x7FFFFFFF7FFFFFFFull;
    uint64_t p2 = bc2(-0.0012624911f);
    p2 = f2fma(p2, t2, bc2( 0.0066700901f));
    p2 = f2fma(p2, t2, bc2(-0.0170881256f));
    p2 = f2fma(p2, t2, bc2( 0.0308918810f));
    p2 = f2fma(p2, t2, bc2(-0.0501743046f));
    p2 = f2fma(p2, t2, bc2( 0.0889789874f));
    p2 = f2fma(p2, t2, bc2(-0.2145988016f));
    p2 = f2fma(p2, t2, bc2( 1.5707963050f));
    const uint64_t om2 = f2fma(t2, bc2(-1.0f), bc2(1.0f));   // 1-|c| >= -2e-7
    float omlo, omhi; upk2(om2, omlo, omhi);
    const uint64_t sq2 = pk2(sqrt_ap(fmaxf(omlo, 0.0f)), sqrt_ap(fmaxf(omhi, 0.0f)));
    const uint64_t r2 = f2mul(sq2, p2);                      // acos(|c|)
    // theta = pi/2 - ((pi/2 - r) | signbit(c))
    const uint64_t u2  = f2fma(r2, bc2(-1.0f), bc2(HALF_PI_F));
    const uint64_t cs2 = u2 | (c2 & 0x8000000080000000ull);
    const uint64_t th2 = f2fma(cs2, bc2(-1.0f), bc2(HALF_PI_F));

    // all three gaussian args computed packed
    const uint64_t d02 = f2add(th2, bc2(-THETA0_F));
    const uint64_t aG2 = f2mul(f2mul(d02, bc2(KG_F)), d02);
    const uint64_t dh2 = f2add(th2, bc2(-HALF_PI_F));
    const uint64_t aQ2 = f2mul(f2mul(dh2, bc2(K2_F)), dh2);
    const uint64_t dA2 = f2add(th2, bc2(-PI_F));
    const uint64_t aA2 = f2mul(f2mul(dA2, bc2(K1_F)), dA2);

    float Glo, Ghi, Qlo, Qhi, Alo, Ahi, clo, chi;
    upk2(aG2, Glo, Ghi); upk2(aQ2, Qlo, Qhi);
    upk2(aA2, Alo, Ahi); upk2(c2, clo, chi);

    const float eGlo = ex2f(Glo), eGhi = ex2f(Ghi);
    const float eQlo = ex2f(Qlo), eQhi = ex2f(Qhi);
    const float eAlo = ex2f(Alo), eAhi = ex2f(Ahi);

    if (LAST) { g += eGlo; g = fmaf(0.5f, eGhi, g); }
    else      { g += eGlo + eGhi; }

    // term1 (gt) / term2 packed-val (lt)
    const bool gtlo = clo < COS_THR_F;   // theta > 160 deg
    const bool gthi = chi < COS_THR_F;
    t1 = fmaf(gtlo ? 3.0f : 0.0f, eAlo, t1);
    t1 = fmaf(gthi ? (LAST ? 1.5f : 3.0f) : 0.0f, eAhi, t1);
    const float vlo = gtlo ? 0.0f : fmaf(2.25f, eQlo, 256.0f);
    const float vhi = gthi ? 0.0f : fmaf(2.25f, eQhi, 256.0f);

    vo += vlo + vhi;
    vm += __shfl_sync(FULLMASK, vlo, lane + (32 - O0));
    const float mh = __shfl_sync(FULLMASK, vhi, lane + (32 - O1));
    if (!LAST) vm += mh;
}

__global__ __launch_bounds__(256) void order_param_kernel(
    const float* __restrict__ vecs,  // [C, 32, 3]
    const int*   __restrict__ mask,  // [C, 32] int32 0/1
    float* __restrict__ out,         // [3, C]
    int C)
{
    const int warp_global = (blockIdx.x * blockDim.x + threadIdx.x) >> 5;
    const int lane = threadIdx.x & 31;
    if (warp_global >= C) return;

    const float* vp = vecs + (size_t)warp_global * 96 + lane * 3;
    const bool valid = mask[(size_t)warp_global * 32 + lane] != 0;
    float x = 0.0f, y = 0.0f, z = 1.0f;
    if (valid) { x = vp[0]; y = vp[1]; z = vp[2]; }
    const float inv = rsqrtf(fmaf(x, x, fmaf(y, y, z * z)));
    x *= inv; y *= inv; z *= inv;

    const unsigned mm = __ballot_sync(FULLMASK, valid);

    float S, G, O;

    if (mm == FULLMASK) {
        // ---------- fast path: all 32 neighbors valid ----------
        const uint64_t x2 = bc2(x), y2 = bc2(y), z2 = bc2(z);
        uint64_t s2 = 0;
        float g = 0.0f, t1 = 0.0f, vo = 0.0f, vm = 0.0f;

        pair_step<1, 9,  false>(x2, y2, z2, x, y, z, lane, s2, g, t1, vo, vm);
        pair_step<2, 10, false>(x2, y2, z2, x, y, z, lane, s2, g, t1, vo, vm);
        pair_step<3, 11, false>(x2, y2, z2, x, y, z, lane, s2, g, t1, vo, vm);
        pair_step<4, 12, false>(x2, y2, z2, x, y, z, lane, s2, g, t1, vo, vm);
        pair_step<5, 13, false>(x2, y2, z2, x, y, z, lane, s2, g, t1, vo, vm);
        pair_step<6, 14, false>(x2, y2, z2, x, y, z, lane, s2, g, t1, vo, vm);
        pair_step<7, 15, false>(x2, y2, z2, x, y, z, lane, s2, g, t1, vo, vm);
        pair_step<8, 16, true >(x2, y2, z2, x, y, z, lane, s2, g, t1, vo, vm);

        float slo, shi; upk2(s2, slo, shi);
        S = 2.0f * (slo + shi);
        G = 2.0f * g;
        const float v   = vo + vm;                          // e2s + 256*row_lt
        const float cnt = floorf(fmaf(v, 1.0f / 256.0f, 0.03f));
        const float e2s = fmaf(-256.0f, cnt, v);
        O = fmaf(e2s, cnt - 1.0f, 2.0f * t1);
    } else {
        // ---------- generic path (verified R3 loop) ----------
        const float NEG_I2DLT2 = -1.0f / (2.0f * D_LT_F * D_LT_F);
        const float NEG_I2D12  = -1.0f / (2.0f * D1_F * D1_F);

        float s_acc = 0.0f, g_acc = 0.0f, t1_acc = 0.0f, e2s = 0.0f;
        int row_lt = 0;
        #pragma unroll
        for (int o = 1; o <= 16; o++) {
            const int p = (lane + o) & 31;
            const float vx = __shfl_sync(FULLMASK, x, p);
            const float vy = __shfl_sync(FULLMASK, y, p);
            const float vz = __shfl_sync(FULLMASK, z, p);
            const bool pv = valid && ((mm >> p) & 1u);
            const float w = pv ? 1.0f : 0.0f;

            float c = fmaf(x, vx, fmaf(y, vy, z * vz));
            c = fminf(1.0f, fmaxf(-1.0f, c));
            const float th = acosf(c);

            const float a = c + (1.0f / 3.0f);
            const float s_p = w * a * a;
            const float d0 = th - THETA0_F;
            const float g_p = w * __expf(d0 * d0 * NEG_I2DLT2);
            const float dpi = th - PI_F;
            const float t1_p = (th > THR_F) ? (3.0f * w * __expf(dpi * dpi * NEG_I2D12)) : 0.0f;
            const bool lt = pv && (th < THR_F);
            const float dh = th - HALF_PI_F;
            const float e2_p = lt ? (2.25f * __expf(dh * dh * NEG_I2DLT2)) : 0.0f;
            const unsigned ltm = __ballot_sync(FULLMASK, lt);

            if (o < 16) {
                s_acc += s_p; g_acc += g_p; t1_acc += t1_p;
                const int q = (lane - o) & 31;
                e2s += e2_p + __shfl_sync(FULLMASK, e2_p, q);
                row_lt += (int)((ltm >> lane) & 1u) + (int)((ltm >> q) & 1u);
            } else {
                s_acc  = fmaf(0.5f, s_p,  s_acc);
                g_acc  = fmaf(0.5f, g_p,  g_acc);
                t1_acc = fmaf(0.5f, t1_p, t1_acc);
                e2s += e2_p;
                row_lt += (int)((ltm >> lane) & 1u);
            }
        }
        S = 2.0f * s_acc;
        G = 2.0f * g_acc;
        O = fmaf(e2s, (float)(row_lt - 1), 2.0f * t1_acc);
    }

    #pragma unroll
    for (int off = 16; off > 0; off >>= 1) {
        S += __shfl_xor_sync(FULLMASK, S, off);
        G += __shfl_xor_sync(FULLMASK, G, off);
        O += __shfl_xor_sync(FULLMASK, O, off);
    }

    if (lane == 0) {
        const float n   = (float)__popc(mm);
        const float nn1 = n * (n - 1.0f);
        out[warp_global]         = 1.0f - 3.0f * S / nn1;
        out[C + warp_global]     = G / nn1;
        out[2 * C + warp_global] = O / (n * (3.0f + (n - 2.0f) * (n - 3.0f)));
    }
}

extern "C" void kernel_launch(void* const* d_in, const int* in_sizes, int n_in,
                              void* d_out, int out_size) {
    const float* vecs = (const float*)d_in[0];
    const int*   mask = (const int*)d_in[1];
    float* out = (float*)d_out;
    const int C = in_sizes[0] / (32 * 3);

    const int warps_per_block = 8;   // 256 threads
    const int blocks = (C + warps_per_block - 1) / warps_per_block;
    order_param_kernel<<<blocks, 256>>>(vecs, mask, out, C);
}